// round 1
// baseline (speedup 1.0000x reference)
#include <cuda_runtime.h>
#include <math.h>

// ---------------------------------------------------------------------------
// MSEObserver: search over 100 range-shrink steps x 16 zero-points for the
// 4-bit quantization clip range minimizing MSE on a 1024x4096 fp32 tensor.
//
// Strategy: MSE per candidate decomposes over quantization buckets into
//   N*MSE = sum_j [ C_j*(j*s)^2 - 2*(j*s)*S_j ] + const(Sum x^2)
// where C_j / S_j are count / sum of x between thresholds (j +- 0.5)*s.
// Build one fine histogram (2^20 bins) of (count, sum_x) -> prefix scan ->
// evaluate all 1600 candidates with ~32 prefix lookups each.
// Sums are int64 fixed point (2^-26) so atomic accumulation is deterministic.
// ---------------------------------------------------------------------------

#define NBINS    1048576      // 2^20
#define CHUNK    1024
#define NCHUNK   1024         // NBINS / CHUNK
#define NCAND    1600         // 100 iterations x 16 zero points
#define FIXSCALE 67108864.0   // 2^26
#define FIXINV   (1.0 / 67108864.0)

__device__ unsigned int       g_minmax[2];      // encoded-ordered min/max
__device__ unsigned int       g_cnt[NBINS];
__device__ unsigned long long g_sum[NBINS];     // fixed-point sum of x per bin
__device__ unsigned int       g_cntS[NBINS];    // inclusive scan within chunk
__device__ long long          g_sumS[NBINS];
__device__ unsigned int       g_cntC[NCHUNK];   // chunk totals -> exclusive prefix
__device__ long long          g_sumC[NCHUNK];
__device__ double             g_score[NCAND];
__device__ float              g_bmin[NCAND];
__device__ float              g_bmax[NCAND];

__device__ __forceinline__ unsigned int f2key(float f) {
    unsigned int u = __float_as_uint(f);
    return (u & 0x80000000u) ? ~u : (u | 0x80000000u);
}
__device__ __forceinline__ float key2f(unsigned int k) {
    unsigned int u = (k & 0x80000000u) ? (k & 0x7FFFFFFFu) : ~k;
    return __uint_as_float(u);
}

// ---------------------------------------------------------------------------
__global__ void k_reset() {
    unsigned int i = blockIdx.x * blockDim.x + threadIdx.x;
    if (i < NBINS) { g_cnt[i] = 0u; g_sum[i] = 0ull; }
    if (i == 0) { g_minmax[0] = 0xFFFFFFFFu; g_minmax[1] = 0u; }
}

// ---------------------------------------------------------------------------
__global__ void k_minmax(const float* __restrict__ x, int n) {
    int n4 = n >> 2;
    const float4* x4 = (const float4*)x;
    float lmin = 3.402823466e38f;
    float lmax = -3.402823466e38f;
    int gid = blockIdx.x * blockDim.x + threadIdx.x;
    int stride = gridDim.x * blockDim.x;
    for (int i = gid; i < n4; i += stride) {
        float4 v = x4[i];
        lmin = fminf(lmin, fminf(fminf(v.x, v.y), fminf(v.z, v.w)));
        lmax = fmaxf(lmax, fmaxf(fmaxf(v.x, v.y), fmaxf(v.z, v.w)));
    }
    if (gid == 0) {  // scalar tail
        for (int i = n4 << 2; i < n; ++i) {
            lmin = fminf(lmin, x[i]);
            lmax = fmaxf(lmax, x[i]);
        }
    }
    #pragma unroll
    for (int o = 16; o > 0; o >>= 1) {
        lmin = fminf(lmin, __shfl_xor_sync(0xFFFFFFFFu, lmin, o));
        lmax = fmaxf(lmax, __shfl_xor_sync(0xFFFFFFFFu, lmax, o));
    }
    __shared__ float smin[8], smax[8];
    int warp = threadIdx.x >> 5, lane = threadIdx.x & 31;
    if (lane == 0) { smin[warp] = lmin; smax[warp] = lmax; }
    __syncthreads();
    if (threadIdx.x == 0) {
        int nw = (blockDim.x + 31) >> 5;
        float m = smin[0], M = smax[0];
        for (int w = 1; w < nw; ++w) { m = fminf(m, smin[w]); M = fmaxf(M, smax[w]); }
        atomicMin(&g_minmax[0], f2key(m));
        atomicMax(&g_minmax[1], f2key(M));
    }
}

// ---------------------------------------------------------------------------
__device__ __forceinline__ void hist_one(float f, float xmin, float invw) {
    int b = (int)((f - xmin) * invw);
    b = max(0, min((int)(NBINS - 1), b));
    long long fx = llrint((double)f * FIXSCALE);  // exact fp32->fixed, 0.5ulp(2^-26)
    atomicAdd(&g_cnt[b], 1u);
    atomicAdd(&g_sum[b], (unsigned long long)fx);
}

__global__ void k_hist(const float* __restrict__ x, int n) {
    float xmin = key2f(g_minmax[0]);
    float xmax = key2f(g_minmax[1]);
    float invw = (float)NBINS / (xmax - xmin);
    int n4 = n >> 2;
    const float4* x4 = (const float4*)x;
    int gid = blockIdx.x * blockDim.x + threadIdx.x;
    int stride = gridDim.x * blockDim.x;
    for (int i = gid; i < n4; i += stride) {
        float4 v = x4[i];
        hist_one(v.x, xmin, invw);
        hist_one(v.y, xmin, invw);
        hist_one(v.z, xmin, invw);
        hist_one(v.w, xmin, invw);
    }
    if (gid == 0) {
        for (int i = n4 << 2; i < n; ++i) hist_one(x[i], xmin, invw);
    }
}

// ---------------------------------------------------------------------------
// Per-chunk inclusive scan (Hillis-Steele), write chunk totals.
__global__ void k_scan1() {
    __shared__ unsigned int sc[CHUNK];
    __shared__ long long ss[CHUNK];
    int t = threadIdx.x;
    int base = blockIdx.x * CHUNK;
    sc[t] = g_cnt[base + t];
    ss[t] = (long long)g_sum[base + t];
    __syncthreads();
    for (int off = 1; off < CHUNK; off <<= 1) {
        unsigned int ac = 0; long long as = 0;
        if (t >= off) { ac = sc[t - off]; as = ss[t - off]; }
        __syncthreads();
        sc[t] += ac; ss[t] += as;
        __syncthreads();
    }
    g_cntS[base + t] = sc[t];
    g_sumS[base + t] = ss[t];
    if (t == CHUNK - 1) { g_cntC[blockIdx.x] = sc[t]; g_sumC[blockIdx.x] = ss[t]; }
}

// Scan chunk totals -> exclusive prefixes (in place).
__global__ void k_scan2() {
    __shared__ unsigned int sc[NCHUNK];
    __shared__ long long ss[NCHUNK];
    int t = threadIdx.x;
    sc[t] = g_cntC[t];
    ss[t] = g_sumC[t];
    __syncthreads();
    for (int off = 1; off < NCHUNK; off <<= 1) {
        unsigned int ac = 0; long long as = 0;
        if (t >= off) { ac = sc[t - off]; as = ss[t - off]; }
        __syncthreads();
        sc[t] += ac; ss[t] += as;
        __syncthreads();
    }
    g_cntC[t] = (t > 0) ? sc[t - 1] : 0u;
    g_sumC[t] = (t > 0) ? ss[t - 1] : 0ll;
}

// Exclusive prefix over bins: count/sum of all bins with index < b, b in [0, NBINS].
__device__ __forceinline__ void lookupP(int b, unsigned int& pc, long long& ps) {
    if (b <= 0) { pc = 0u; ps = 0ll; return; }
    if (b > NBINS) b = NBINS;
    int bb = b - 1;
    int ch = bb >> 10;
    pc = g_cntC[ch] + g_cntS[bb];
    ps = g_sumC[ch] + g_sumS[bb];
}

// ---------------------------------------------------------------------------
// Evaluate all 1600 candidates analytically from prefix sums.
__global__ void k_eval() {
    int c = blockIdx.x * blockDim.x + threadIdx.x;
    if (c >= NCAND) return;

    float xmin = key2f(g_minmax[0]);
    float xmax = key2f(g_minmax[1]);
    float xrange = __fsub_rn(xmax, xmin);

    int ii = (c >> 4) + 1;     // iteration 1..100
    int zi = c & 15;           // zero-point loop var 0..15
    float fi = (float)ii;
    float zf = (float)zi;

    // Replicate reference fp32 candidate-parameter math exactly.
    float tmp_max = __fmul_rn(__fdiv_rn(xrange, 100.0f), fi);
    float delta   = __fdiv_rn(tmp_max, 15.0f);
    float nmin    = fmaxf(__fmul_rn(-zf, delta), xmin);
    float nmax    = fminf(__fsub_rn(tmp_max, __fmul_rn(zf, delta)), xmax);
    float min_neg = fminf(nmin, 0.0f);
    float max_pos = fmaxf(nmax, 0.0f);
    float scale   = fmaxf(__fdiv_rn(__fsub_rn(max_pos, min_neg), 15.0f), 1.1920929e-7f);
    float zr      = rintf(__fdiv_rn(min_neg, scale));         // round half-even
    float zpc     = fminf(fmaxf(-zr, 0.0f), 15.0f);           // clip(0 - round, 0, 15)
    int zp = (int)zpc;
    int lo = -zp, hi = 15 - zp;

    double s     = (double)scale;
    double xminD = (double)xmin;
    double invwD = (double)NBINS / (double)xrange;

    double score = 0.0;
    unsigned int pc_prev = 0u;
    long long ps_prev = 0ll;
    #pragma unroll 1
    for (int j = lo; j <= hi; ++j) {
        int bt;
        if (j == hi) {
            bt = NBINS;
        } else {
            double t = ((double)j + 0.5) * s;          // upper threshold of bucket j
            double bf = (t - xminD) * invwD;
            bt = (int)floor(bf);
            bt = max(0, min((int)NBINS, bt));
        }
        unsigned int pc; long long ps;
        lookupP(bt, pc, ps);
        double C = (double)(pc - pc_prev);
        double S = (double)(ps - ps_prev) * FIXINV;    // sum of x in bucket j
        double v = (double)j * s;                       // reconstructed value
        score += C * v * v - 2.0 * v * S;               // sum (xq^2 - 2 xq x)
        pc_prev = pc; ps_prev = ps;
    }
    g_score[c] = score;
    g_bmin[c] = nmin;
    g_bmax[c] = nmax;
}

// ---------------------------------------------------------------------------
// Lexicographic-first strict minimum over candidates == reference's
// per-iteration argmin + strict '<' cross-iteration update.
__global__ void k_select(float* __restrict__ out) {
    __shared__ double ssc[256];
    __shared__ int sid[256];
    int t = threadIdx.x;
    double best = 1.0e300;
    int bi = NCAND;
    for (int c = t; c < NCAND; c += 256) {
        double sc = g_score[c];
        if (sc < best) { best = sc; bi = c; }   // ascending c -> first min per thread
    }
    ssc[t] = best; sid[t] = bi;
    __syncthreads();
    for (int o = 128; o > 0; o >>= 1) {
        if (t < o) {
            double s2 = ssc[t + o]; int i2 = sid[t + o];
            if (s2 < ssc[t] || (s2 == ssc[t] && i2 < sid[t])) { ssc[t] = s2; sid[t] = i2; }
        }
        __syncthreads();
    }
    if (t == 0) {
        int b = sid[0];
        out[0] = g_bmin[b];
        out[1] = g_bmax[b];
    }
}

// ---------------------------------------------------------------------------
extern "C" void kernel_launch(void* const* d_in, const int* in_sizes, int n_in,
                              void* d_out, int out_size) {
    const float* x = (const float*)d_in[0];
    int n = in_sizes[0];
    int n4 = n >> 2;

    k_reset<<<(NBINS + 255) / 256, 256>>>();
    k_minmax<<<512, 256>>>(x, n);
    {
        int blocks = (n4 + 255) / 256;
        if (blocks < 1) blocks = 1;
        if (blocks > 16384) blocks = 16384;
        k_hist<<<blocks, 256>>>(x, n);
    }
    k_scan1<<<NCHUNK, CHUNK>>>();
    k_scan2<<<1, NCHUNK>>>();
    k_eval<<<(NCAND + 255) / 256, 256>>>();
    k_select<<<1, 256>>>((float*)d_out);
}

// round 2
// speedup vs baseline: 1.7926x; 1.7926x over previous
#include <cuda_runtime.h>
#include <math.h>
#include <float.h>

// ---------------------------------------------------------------------------
// MSEObserver: search 100 range-shrink steps x 16 zero-points for the 4-bit
// quantization clip range minimizing MSE on a 1024x4096 fp32 tensor.
//
//   N*MSE(cand) = sum_j [ C_j*(j*s)^2 - 2*(j*s)*S_j ] + const
//
// One packed histogram (2^19 bins, u64 = count<<42 | (fix26(x)+2^29 biased
// sum)) -> warp-shuffle prefix scan -> analytic evaluation of all 1600
// candidates (16 buckets = 16 lanes) -> fused last-block argmin select.
// All atomics are integer => deterministic across replays.
// ---------------------------------------------------------------------------

#define NBINS    524288       // 2^19
#define NCHUNK   512          // NBINS / 1024
#define NCAND    1600
#define INITB    256          // blocks in k_init (minmax partials)
#define MASK42   ((1ull << 42) - 1ull)
#define FIXINV   (1.0 / 67108864.0)

__device__ unsigned long long g_hist[NBINS];    // packed count|biased-sum
__device__ unsigned int       g_cntS[NBINS];    // inclusive scan within chunk
__device__ long long          g_sumS[NBINS];
__device__ unsigned int       g_cntC[NCHUNK];   // exclusive chunk prefixes
__device__ long long          g_sumC[NCHUNK];
__device__ float              g_pmin[INITB];    // per-block minmax partials
__device__ float              g_pmax[INITB];
__device__ double             g_score[NCAND];
__device__ float              g_bmin[NCAND];
__device__ float              g_bmax[NCAND];
__device__ unsigned int       g_done;

// ---------------------------------------------------------------------------
// init: zero histogram + per-block min/max partials + reset done counter
__global__ void k_init(const float* __restrict__ x, int n) {
    int gid = blockIdx.x * blockDim.x + threadIdx.x;
    int stride = gridDim.x * blockDim.x;
    for (int i = gid; i < NBINS; i += stride) g_hist[i] = 0ull;
    if (gid == 0) g_done = 0u;

    int n4 = n >> 2;
    const float4* x4 = (const float4*)x;
    float m = FLT_MAX, M = -FLT_MAX;
    for (int i = gid; i < n4; i += stride) {
        float4 v = x4[i];
        m = fminf(m, fminf(fminf(v.x, v.y), fminf(v.z, v.w)));
        M = fmaxf(M, fmaxf(fmaxf(v.x, v.y), fmaxf(v.z, v.w)));
    }
    if (gid == 0) {
        for (int i = n4 << 2; i < n; ++i) { m = fminf(m, x[i]); M = fmaxf(M, x[i]); }
    }
    #pragma unroll
    for (int o = 16; o > 0; o >>= 1) {
        m = fminf(m, __shfl_xor_sync(0xFFFFFFFFu, m, o));
        M = fmaxf(M, __shfl_xor_sync(0xFFFFFFFFu, M, o));
    }
    __shared__ float sm[8], sM[8];
    int w = threadIdx.x >> 5, lane = threadIdx.x & 31;
    if (lane == 0) { sm[w] = m; sM[w] = M; }
    __syncthreads();
    if (threadIdx.x == 0) {
        int nw = blockDim.x >> 5;
        float a = sm[0], b = sM[0];
        for (int i = 1; i < nw; ++i) { a = fminf(a, sm[i]); b = fmaxf(b, sM[i]); }
        g_pmin[blockIdx.x] = a;
        g_pmax[blockIdx.x] = b;
    }
}

// Reduce the INITB minmax partials inside a block (warp 0), broadcast via smem.
__device__ __forceinline__ void load_minmax(float& xmin, float& xmax) {
    __shared__ float s_min, s_max;
    if (threadIdx.x < 32) {
        float m = FLT_MAX, M = -FLT_MAX;
        for (int i = threadIdx.x; i < INITB; i += 32) {
            m = fminf(m, g_pmin[i]);
            M = fmaxf(M, g_pmax[i]);
        }
        #pragma unroll
        for (int o = 16; o > 0; o >>= 1) {
            m = fminf(m, __shfl_xor_sync(0xFFFFFFFFu, m, o));
            M = fmaxf(M, __shfl_xor_sync(0xFFFFFFFFu, M, o));
        }
        if (threadIdx.x == 0) { s_min = m; s_max = M; }
    }
    __syncthreads();
    xmin = s_min;
    xmax = s_max;
}

// ---------------------------------------------------------------------------
__device__ __forceinline__ void hist_one(float f, float xmin, float invw) {
    int b = (int)((f - xmin) * invw);
    b = max(0, min((int)(NBINS - 1), b));
    // f * 2^26 is EXACT (power-of-2 scaling); llrintf rounds-to-nearest-even.
    long long fx = llrintf(f * 67108864.0f);
    unsigned long long p = (1ull << 42) + (unsigned long long)(fx + 536870912ll);
    atomicAdd(&g_hist[b], p);
}

__global__ void k_hist(const float* __restrict__ x, int n) {
    float xmin, xmax;
    load_minmax(xmin, xmax);
    float invw = (float)NBINS / (xmax - xmin);
    int n4 = n >> 2;
    const float4* x4 = (const float4*)x;
    int gid = blockIdx.x * blockDim.x + threadIdx.x;
    int stride = gridDim.x * blockDim.x;
    for (int i = gid; i < n4; i += stride) {
        float4 v = x4[i];
        hist_one(v.x, xmin, invw);
        hist_one(v.y, xmin, invw);
        hist_one(v.z, xmin, invw);
        hist_one(v.w, xmin, invw);
    }
    if (gid == 0) {
        for (int i = n4 << 2; i < n; ++i) hist_one(x[i], xmin, invw);
    }
}

// ---------------------------------------------------------------------------
// Per-chunk (1024-bin) inclusive scan via warp shuffles + warp-total scan.
__global__ void k_scan1() {
    __shared__ unsigned int wc[32];
    __shared__ long long ws[32];
    int t = threadIdx.x, lane = t & 31, w = t >> 5;
    int idx = blockIdx.x * 1024 + t;

    unsigned long long p = g_hist[idx];
    unsigned int cnt = (unsigned int)(p >> 42);
    long long sum = (long long)(p & MASK42) - ((long long)cnt << 29);

    #pragma unroll
    for (int off = 1; off < 32; off <<= 1) {
        unsigned int c2 = __shfl_up_sync(0xFFFFFFFFu, cnt, off);
        long long s2 = __shfl_up_sync(0xFFFFFFFFu, sum, off);
        if (lane >= off) { cnt += c2; sum += s2; }
    }
    if (lane == 31) { wc[w] = cnt; ws[w] = sum; }
    __syncthreads();
    if (w == 0) {
        unsigned int c = wc[lane];
        long long s = ws[lane];
        #pragma unroll
        for (int off = 1; off < 32; off <<= 1) {
            unsigned int c2 = __shfl_up_sync(0xFFFFFFFFu, c, off);
            long long s2 = __shfl_up_sync(0xFFFFFFFFu, s, off);
            if (lane >= off) { c += c2; s += s2; }
        }
        wc[lane] = c; ws[lane] = s;
    }
    __syncthreads();
    if (w > 0) { cnt += wc[w - 1]; sum += ws[w - 1]; }
    g_cntS[idx] = cnt;
    g_sumS[idx] = sum;
    if (t == 1023) { g_cntC[blockIdx.x] = cnt; g_sumC[blockIdx.x] = sum; }
}

// Scan the 512 chunk totals -> exclusive prefixes (in place).
__global__ void k_scan2() {
    __shared__ unsigned int wc[32];
    __shared__ long long ws[32];
    int t = threadIdx.x, lane = t & 31, w = t >> 5;   // 512 threads, 16 warps
    unsigned int oc = g_cntC[t];
    long long os = g_sumC[t];
    unsigned int cnt = oc;
    long long sum = os;
    #pragma unroll
    for (int off = 1; off < 32; off <<= 1) {
        unsigned int c2 = __shfl_up_sync(0xFFFFFFFFu, cnt, off);
        long long s2 = __shfl_up_sync(0xFFFFFFFFu, sum, off);
        if (lane >= off) { cnt += c2; sum += s2; }
    }
    if (lane == 31) { wc[w] = cnt; ws[w] = sum; }
    __syncthreads();
    if (w == 0) {
        unsigned int c = (lane < 16) ? wc[lane] : 0u;
        long long s = (lane < 16) ? ws[lane] : 0ll;
        #pragma unroll
        for (int off = 1; off < 32; off <<= 1) {
            unsigned int c2 = __shfl_up_sync(0xFFFFFFFFu, c, off);
            long long s2 = __shfl_up_sync(0xFFFFFFFFu, s, off);
            if (lane >= off) { c += c2; s += s2; }
        }
        if (lane < 16) { wc[lane] = c; ws[lane] = s; }
    }
    __syncthreads();
    if (w > 0) { cnt += wc[w - 1]; sum += ws[w - 1]; }
    g_cntC[t] = cnt - oc;   // exclusive
    g_sumC[t] = sum - os;
}

// Exclusive prefix over bins (count/sum of bins with index < b), b in [0,NBINS].
__device__ __forceinline__ void lookupP(int b, unsigned int& pc, long long& ps) {
    if (b <= 0) { pc = 0u; ps = 0ll; return; }
    if (b > NBINS) b = NBINS;
    int bb = b - 1;
    int ch = bb >> 10;
    pc = g_cntC[ch] + g_cntS[bb];
    ps = g_sumC[ch] + g_sumS[bb];
}

// ---------------------------------------------------------------------------
// Evaluate all 1600 candidates: 16 buckets = 16 lanes, 2 candidates per warp.
// Last-finishing block performs the lexicographic-first argmin select.
__global__ void k_evalsel(float* __restrict__ out) {
    float xmin, xmax;
    load_minmax(xmin, xmax);
    float xrange = __fsub_rn(xmax, xmin);

    int t = threadIdx.x, lane = t & 31, w = t >> 5;
    int l = lane & 15;                       // bucket index within candidate
    int c = blockIdx.x * 64 + w * 2 + (lane >> 4);   // 25 blocks x 64 cands

    int ii = (c >> 4) + 1;   // iteration 1..100
    int zi = c & 15;         // zero-point loop var 0..15
    float fi = (float)ii;
    float zf = (float)zi;

    // Replicate reference fp32 candidate-parameter math exactly.
    float tmp_max = __fmul_rn(__fdiv_rn(xrange, 100.0f), fi);
    float delta   = __fdiv_rn(tmp_max, 15.0f);
    float nmin    = fmaxf(__fmul_rn(-zf, delta), xmin);
    float nmax    = fminf(__fsub_rn(tmp_max, __fmul_rn(zf, delta)), xmax);
    float min_neg = fminf(nmin, 0.0f);
    float max_pos = fmaxf(nmax, 0.0f);
    float scale   = fmaxf(__fdiv_rn(__fsub_rn(max_pos, min_neg), 15.0f), 1.1920929e-7f);
    float zr      = rintf(__fdiv_rn(min_neg, scale));
    float zpc     = fminf(fmaxf(-zr, 0.0f), 15.0f);
    int zp = (int)zpc;
    int j = -zp + l;                       // this lane's bucket level

    double s     = (double)scale;
    double xminD = (double)xmin;
    double invwD = (double)NBINS / (double)xrange;

    // Upper-threshold bin for bucket j (lane 15 -> +inf).
    int bt;
    if (l == 15) {
        bt = NBINS;
    } else {
        double th = ((double)j + 0.5) * s;
        double bf = (th - xminD) * invwD;
        bt = (int)floor(bf);
        bt = max(0, min((int)NBINS, bt));
    }
    unsigned int pc_u; long long ps_u;
    lookupP(bt, pc_u, ps_u);

    // Lower-threshold prefix = previous lane's upper (lane l==0 -> 0).
    unsigned int pc_l = __shfl_up_sync(0xFFFFFFFFu, pc_u, 1);
    long long    ps_l = __shfl_up_sync(0xFFFFFFFFu, ps_u, 1);
    if (l == 0) { pc_l = 0u; ps_l = 0ll; }

    double C = (double)(pc_u - pc_l);
    double S = (double)(ps_u - ps_l) * FIXINV;
    double v = (double)j * s;
    double term = C * v * v - 2.0 * v * S;

    #pragma unroll
    for (int off = 1; off < 16; off <<= 1)
        term += __shfl_xor_sync(0xFFFFFFFFu, term, off);

    if (l == 0) {
        g_score[c] = term;
        g_bmin[c] = nmin;
        g_bmax[c] = nmax;
    }

    // ---- fused select: last block to finish does the argmin ----
    __shared__ bool s_last;
    __syncthreads();
    if (t == 0) {
        __threadfence();
        s_last = (atomicAdd(&g_done, 1u) == gridDim.x - 1);
    }
    __syncthreads();
    if (!s_last) return;

    __shared__ double ssc[1024];
    __shared__ int sid[1024];
    double best = 1.0e300;
    int bi = NCAND;
    for (int cc = t; cc < NCAND; cc += 1024) {
        double sc = g_score[cc];
        if (sc < best) { best = sc; bi = cc; }   // ascending -> first strict min
    }
    ssc[t] = best; sid[t] = bi;
    __syncthreads();
    for (int o = 512; o > 0; o >>= 1) {
        if (t < o) {
            double s2 = ssc[t + o]; int i2 = sid[t + o];
            if (s2 < ssc[t] || (s2 == ssc[t] && i2 < sid[t])) { ssc[t] = s2; sid[t] = i2; }
        }
        __syncthreads();
    }
    if (t == 0) {
        int b = sid[0];
        out[0] = g_bmin[b];
        out[1] = g_bmax[b];
    }
}

// ---------------------------------------------------------------------------
extern "C" void kernel_launch(void* const* d_in, const int* in_sizes, int n_in,
                              void* d_out, int out_size) {
    const float* x = (const float*)d_in[0];
    int n = in_sizes[0];

    k_init<<<INITB, 256>>>(x, n);
    k_hist<<<2048, 256>>>(x, n);
    k_scan1<<<NCHUNK, 1024>>>();
    k_scan2<<<1, 512>>>();
    k_evalsel<<<25, 1024>>>((float*)d_out);
}